// round 4
// baseline (speedup 1.0000x reference)
#include <cuda_runtime.h>
#include <math.h>
#include <float.h>

#define B_   16
#define C_   64
#define N_   2048
#define K_   20
#define OUT_ 128
#define G_   (B_*N_)          // 32768 columns
#define TN   8                // columns per block
#define NBLK (G_/TN)          // 4096
#define THR  256
#define FSTR 1284             // padded per-column stride (floats)
#define XSTR 68               // padded x-row stride (floats)
#define EPS_ 1e-5f

typedef unsigned long long u64;

// ---- packed fp32x2 helpers (sm_100+ only; ptxas never auto-fuses) ----
__device__ __forceinline__ u64 fma2(u64 a, u64 b, u64 c){
    u64 d; asm("fma.rn.f32x2 %0, %1, %2, %3;" : "=l"(d) : "l"(a), "l"(b), "l"(c)); return d;
}
__device__ __forceinline__ u64 pack2(float lo, float hi){
    u64 d; asm("mov.b64 %0, {%1,%2};" : "=l"(d) : "f"(lo), "f"(hi)); return d;
}
__device__ __forceinline__ float sum2(u64 d){
    float a, b; asm("mov.b64 {%0,%1}, %2;" : "=f"(a), "=f"(b) : "l"(d)); return a + b;
}

// ---- device scratch (no allocations allowed) ----
__device__ float g_xT[G_*C_];             // 8 MB: x transposed to (B*N, C)
__device__ float g_part[NBLK*OUT_*2];     // 4 MB: per-block (sum, sumsq) per channel
__device__ float g_scale[OUT_];
__device__ float g_shift[OUT_];

// ============================================================
// Kernel 0: transpose x (B,C,N) -> xT (B*N, C), smem-tiled
// ============================================================
__global__ void transpose_k(const float* __restrict__ x) {
    __shared__ float t[32][33];
    int b  = blockIdx.z;
    int n0 = blockIdx.x * 32, c0 = blockIdx.y * 32;
    int tx = threadIdx.x, ty = threadIdx.y;
    #pragma unroll
    for (int i = ty; i < 32; i += 8)
        t[i][tx] = x[((size_t)b*C_ + c0 + i)*N_ + n0 + tx];
    __syncthreads();
    #pragma unroll
    for (int i = ty; i < 32; i += 8)
        g_xT[((size_t)b*N_ + n0 + i)*C_ + c0 + tx] = t[tx][i];
}

// ============================================================
// Kernel 1: fused gather + feats + out2 + out4 (pre-BN) + partial stats
// thread map (compute phase): col = tid&7, o-quad = (tid>>3)&15, h = tid>>7
//   each thread computes 4 output rows {oq, oq+16, oq+32, oq+48} for one
//   column, over HALF the reduction (out2/dx) or half the k range (out4);
//   halves combined through smem scratch.
// ============================================================
__global__ __launch_bounds__(THR, 2)
void main_k(const int*   __restrict__ sidx,
            const float* __restrict__ adjw,
            const float* __restrict__ W2,
            const float* __restrict__ b2,
            const float* __restrict__ W4,
            float*       __restrict__ out)
{
    extern __shared__ float sm[];
    float* S  = sm;                      // TN*FSTR: S[col][i*64+f]
    float* F  = S + TN*FSTR;             // TN*FSTR: feats[col][f*20+k]; later scratch
    float* AW = F + TN*FSTR;             // 64*68: first A[col*400+..], later W4a rows (stride 68)
    float* XR = AW + 64*68;              // TN*XSTR: x row per column

    const int tid = threadIdx.x;
    const int g0  = blockIdx.x * TN;

    // ---- gather spiral rows into S (float4, coalesced over xT rows) ----
    for (int j = tid; j < TN*K_*16; j += THR) {
        int col = j / (K_*16);
        int r   = j % (K_*16);
        int i   = r >> 4, q = r & 15;
        int p   = sidx[(g0 + col)*K_ + i];
        float4 v = ((const float4*)g_xT)[(size_t)p*16 + q];
        float* d = &S[col*FSTR + i*64 + q*4];
        d[0]=v.x; d[1]=v.y; d[2]=v.z; d[3]=v.w;
    }
    // ---- adjweight tile ----
    for (int j = tid; j < TN*100; j += THR) {
        int col = j/100, q = j%100;
        float4 v = ((const float4*)adjw)[(size_t)(g0+col)*100 + q];
        float* d = &AW[col*400 + q*4];
        d[0]=v.x; d[1]=v.y; d[2]=v.z; d[3]=v.w;
    }
    // ---- x rows (padded stride XSTR) ----
    for (int j = tid; j < TN*16; j += THR) {
        float4 v = ((const float4*)g_xT)[(size_t)(g0 + j/16)*16 + (j & 15)];
        float* d = &XR[(j/16)*XSTR + (j & 15)*4];
        d[0]=v.x; d[1]=v.y; d[2]=v.z; d[3]=v.w;
    }
    __syncthreads();

    // ---- feats[col][f*20+k] = sum_i S[col][i][f] * A[col][i][k] (f32x2 over k)
    #pragma unroll
    for (int pass = 0; pass < 2; pass++) {
        int id  = tid + pass*THR;
        int fcol = id >> 6, f = id & 63;
        u64 acc[10];
        #pragma unroll
        for (int k = 0; k < 10; k++) acc[k] = 0ull;
        const float* Sc = S + fcol*FSTR + f;
        const u64*   Ac = (const u64*)(AW + fcol*400);   // broadcast across warp lanes
        #pragma unroll
        for (int i = 0; i < 20; i++) {
            float s = Sc[i*64];
            u64 sv = pack2(s, s);
            #pragma unroll
            for (int k = 0; k < 10; k++) acc[k] = fma2(sv, Ac[i*10 + k], acc[k]);
        }
        u64* Fd = (u64*)(F + fcol*FSTR + f*20);
        #pragma unroll
        for (int k = 0; k < 10; k++) Fd[k] = acc[k];
    }
    __syncthreads();

    // ---- stage W4a (first 64 cols of W4) into AW, padded stride 68 ----
    for (int j = tid; j < 64*16; j += THR) {
        int o = j >> 4, q = j & 15;
        float4 v = ((const float4*)W4)[o*32 + q];
        float* d = &AW[o*XSTR + q*4];
        d[0]=v.x; d[1]=v.y; d[2]=v.z; d[3]=v.w;
    }
    __syncthreads();

    const int col = tid & 7;
    const int oq  = (tid >> 3) & 15;
    const int h   = tid >> 7;                    // reduction/k half
    const int g   = g0 + col;
    const int r0 = oq, r1 = oq+16, r2 = oq+32, r3 = oq+48;

    // ================= out2 half: W2 rows {r0..r3} x F[col], q in [h*160,h*160+160)
    float o2p[4];
    {
        const ulonglong2* fv = (const ulonglong2*)(F + col*FSTR) + h*160;
        const ulonglong2* w0 = (const ulonglong2*)(W2 + (size_t)r0*1280) + h*160;
        const ulonglong2* w1 = (const ulonglong2*)(W2 + (size_t)r1*1280) + h*160;
        const ulonglong2* w2 = (const ulonglong2*)(W2 + (size_t)r2*1280) + h*160;
        const ulonglong2* w3 = (const ulonglong2*)(W2 + (size_t)r3*1280) + h*160;
        u64 a0x=0,a0y=0,a1x=0,a1y=0,a2x=0,a2y=0,a3x=0,a3y=0;
        #pragma unroll 4
        for (int q = 0; q < 160; q++) {
            ulonglong2 fq = fv[q];
            ulonglong2 u0 = w0[q], u1 = w1[q], u2 = w2[q], u3 = w3[q];
            a0x = fma2(fq.x, u0.x, a0x); a0y = fma2(fq.y, u0.y, a0y);
            a1x = fma2(fq.x, u1.x, a1x); a1y = fma2(fq.y, u1.y, a1y);
            a2x = fma2(fq.x, u2.x, a2x); a2y = fma2(fq.y, u2.y, a2y);
            a3x = fma2(fq.x, u3.x, a3x); a3y = fma2(fq.y, u3.y, a3y);
        }
        o2p[0] = sum2(a0x) + sum2(a0y);
        o2p[1] = sum2(a1x) + sum2(a1y);
        o2p[2] = sum2(a2x) + sum2(a2y);
        o2p[3] = sum2(a3x) + sum2(a3y);
    }

    // ================= out4 half: max over k in [h*10, h*10+10), rows {r0..r3}
    float m4[4] = {-FLT_MAX, -FLT_MAX, -FLT_MAX, -FLT_MAX};
    {
        const ulonglong2* wa0 = (const ulonglong2*)(AW + r0*XSTR);
        const ulonglong2* wa1 = (const ulonglong2*)(AW + r1*XSTR);
        const ulonglong2* wa2 = (const ulonglong2*)(AW + r2*XSTR);
        const ulonglong2* wa3 = (const ulonglong2*)(AW + r3*XSTR);
        #pragma unroll
        for (int kc = 0; kc < 2; kc++) {
            u64 s0[5], s1[5], s2[5], s3[5];
            #pragma unroll
            for (int k = 0; k < 5; k++) { s0[k]=0ull; s1[k]=0ull; s2[k]=0ull; s3[k]=0ull; }
            const float* Sb = S + col*FSTR + (h*10 + kc*5)*64;
            #pragma unroll
            for (int q = 0; q < 16; q++) {
                ulonglong2 u0 = wa0[q], u1 = wa1[q], u2 = wa2[q], u3 = wa3[q];
                #pragma unroll
                for (int k = 0; k < 5; k++) {
                    ulonglong2 sv = ((const ulonglong2*)(Sb + k*64))[q];
                    s0[k] = fma2(sv.x, u0.x, s0[k]); s0[k] = fma2(sv.y, u0.y, s0[k]);
                    s1[k] = fma2(sv.x, u1.x, s1[k]); s1[k] = fma2(sv.y, u1.y, s1[k]);
                    s2[k] = fma2(sv.x, u2.x, s2[k]); s2[k] = fma2(sv.y, u2.y, s2[k]);
                    s3[k] = fma2(sv.x, u3.x, s3[k]); s3[k] = fma2(sv.y, u3.y, s3[k]);
                }
            }
            #pragma unroll
            for (int k = 0; k < 5; k++) {
                m4[0] = fmaxf(m4[0], sum2(s0[k]));
                m4[1] = fmaxf(m4[1], sum2(s1[k]));
                m4[2] = fmaxf(m4[2], sum2(s2[k]));
                m4[3] = fmaxf(m4[3], sum2(s3[k]));
            }
        }
    }

    // ================= dx half: (W4b - W4a) @ x[:,n], c in [h*32, h*32+32)
    float dxp[4];
    {
        const ulonglong2* xv  = (const ulonglong2*)(XR + col*XSTR) + h*8;
        const ulonglong2* wr0 = (const ulonglong2*)(W4 + (size_t)r0*128);
        const ulonglong2* wr1 = (const ulonglong2*)(W4 + (size_t)r1*128);
        const ulonglong2* wr2 = (const ulonglong2*)(W4 + (size_t)r2*128);
        const ulonglong2* wr3 = (const ulonglong2*)(W4 + (size_t)r3*128);
        u64 aA0=0,aA1=0,aA2=0,aA3=0, aB0=0,aB1=0,aB2=0,aB3=0;
        #pragma unroll
        for (int q = 0; q < 8; q++) {
            ulonglong2 x2 = xv[q];
            ulonglong2 A0 = wr0[h*8+q], Bv0 = wr0[16+h*8+q];
            ulonglong2 A1 = wr1[h*8+q], Bv1 = wr1[16+h*8+q];
            ulonglong2 A2 = wr2[h*8+q], Bv2 = wr2[16+h*8+q];
            ulonglong2 A3 = wr3[h*8+q], Bv3 = wr3[16+h*8+q];
            aA0 = fma2(x2.x, A0.x, aA0); aA0 = fma2(x2.y, A0.y, aA0);
            aB0 = fma2(x2.x, Bv0.x, aB0); aB0 = fma2(x2.y, Bv0.y, aB0);
            aA1 = fma2(x2.x, A1.x, aA1); aA1 = fma2(x2.y, A1.y, aA1);
            aB1 = fma2(x2.x, Bv1.x, aB1); aB1 = fma2(x2.y, Bv1.y, aB1);
            aA2 = fma2(x2.x, A2.x, aA2); aA2 = fma2(x2.y, A2.y, aA2);
            aB2 = fma2(x2.x, Bv2.x, aB2); aB2 = fma2(x2.y, Bv2.y, aB2);
            aA3 = fma2(x2.x, A3.x, aA3); aA3 = fma2(x2.y, A3.y, aA3);
            aB3 = fma2(x2.x, Bv3.x, aB3); aB3 = fma2(x2.y, Bv3.y, aB3);
        }
        dxp[0] = sum2(aB0) - sum2(aA0);
        dxp[1] = sum2(aB1) - sum2(aA1);
        dxp[2] = sum2(aB2) - sum2(aA2);
        dxp[3] = sum2(aB3) - sum2(aA3);
    }

    // ================= combine halves through scratch (reuse F region)
    __syncthreads();                       // all reads of F/S done
    float* sc = F;
    {
        float* mine = sc + tid*12;
        #pragma unroll
        for (int j = 0; j < 4; j++) {
            mine[j]     = o2p[j];
            mine[4 + j] = m4[j];
            mine[8 + j] = dxp[j];
        }
    }
    __syncthreads();

    if (tid < 128) {                       // h==0 threads finalize; warps 0-3 fully active
        const float* pr = sc + (tid + 128)*12;
        const int rr[4] = {r0, r1, r2, r3};
        float v2[4], v4[4];
        #pragma unroll
        for (int j = 0; j < 4; j++) {
            v2[j] = o2p[j] + pr[j] + b2[rr[j]];
            v4[j] = fmaxf(m4[j], pr[4 + j]) + dxp[j] + pr[8 + j];
        }
        // ---- write pre-BN outputs ----
        int b = g >> 11, n = g & 2047;
        size_t base = ((size_t)b*OUT_)*N_ + n;
        #pragma unroll
        for (int j = 0; j < 4; j++) {
            out[base + (size_t)rr[j]*N_]      = v2[j];
            out[base + (size_t)(64+rr[j])*N_] = v4[j];
        }
        // ---- deterministic per-block stats: butterfly over the 3 col bits ----
        float s[8], q2[8];
        #pragma unroll
        for (int j = 0; j < 4; j++) {
            s[j]   = v2[j]; q2[j]   = v2[j]*v2[j];
            s[4+j] = v4[j]; q2[4+j] = v4[j]*v4[j];
        }
        #pragma unroll
        for (int off = 1; off < 8; off <<= 1) {
            #pragma unroll
            for (int i = 0; i < 8; i++) {
                s[i]  += __shfl_xor_sync(0xffffffffu, s[i],  off);
                q2[i] += __shfl_xor_sync(0xffffffffu, q2[i], off);
            }
        }
        if (col == 0) {
            float* P = g_part + (size_t)blockIdx.x*(OUT_*2);
            #pragma unroll
            for (int j = 0; j < 4; j++) {
                P[rr[j]*2]          = s[j];   P[rr[j]*2 + 1]          = q2[j];
                P[(64+rr[j])*2]     = s[4+j]; P[(64+rr[j])*2 + 1]     = q2[4+j];
            }
        }
    }
}

// ============================================================
// Kernel 2: fixed-order reduction of partials -> scale/shift per channel
// ============================================================
__global__ void reduce_k(const float* __restrict__ gamma, const float* __restrict__ beta) {
    int ch = blockIdx.x;
    __shared__ float ss[256], sq[256];
    float s = 0.f, q = 0.f;
    for (int blk = threadIdx.x; blk < NBLK; blk += 256) {
        const float* P = g_part + (size_t)blk*(OUT_*2) + ch*2;
        s += P[0]; q += P[1];
    }
    ss[threadIdx.x] = s; sq[threadIdx.x] = q;
    __syncthreads();
    for (int off = 128; off > 0; off >>= 1) {
        if (threadIdx.x < off) {
            ss[threadIdx.x] += ss[threadIdx.x + off];
            sq[threadIdx.x] += sq[threadIdx.x + off];
        }
        __syncthreads();
    }
    if (threadIdx.x == 0) {
        float mean = ss[0] / (float)G_;
        float var  = sq[0] / (float)G_ - mean*mean;
        float sc   = gamma[ch] * rsqrtf(var + EPS_);
        g_scale[ch] = sc;
        g_shift[ch] = beta[ch] - mean*sc;
    }
}

// ============================================================
// Kernel 3: apply batchnorm in place (float4)
// ============================================================
__global__ void bn_k(float* __restrict__ out) {
    int i  = blockIdx.x*blockDim.x + threadIdx.x;     // over 1,048,576 float4
    int ch = (i >> 9) & 127;                          // 512 float4 per (b,ch) row
    float sc = g_scale[ch], sh = g_shift[ch];
    float4 v = ((float4*)out)[i];
    v.x = v.x*sc + sh; v.y = v.y*sc + sh;
    v.z = v.z*sc + sh; v.w = v.w*sc + sh;
    ((float4*)out)[i] = v;
}

// ============================================================
extern "C" void kernel_launch(void* const* d_in, const int* in_sizes, int n_in,
                              void* d_out, int out_size) {
    const float* x     = (const float*)d_in[0];
    const int*   sidx  = (const int*)  d_in[1];
    const float* adjw  = (const float*)d_in[2];
    const float* W2    = (const float*)d_in[3];
    const float* b2    = (const float*)d_in[4];
    const float* W4    = (const float*)d_in[5];
    const float* gamma = (const float*)d_in[6];
    const float* beta  = (const float*)d_in[7];
    float* out = (float*)d_out;

    dim3 tb(32, 8);
    dim3 tg(N_/32, C_/32, B_);
    transpose_k<<<tg, tb>>>(x);

    const int smem = (TN*FSTR*2 + 64*XSTR + TN*XSTR) * (int)sizeof(float); // 101,760 B
    cudaFuncSetAttribute(main_k, cudaFuncAttributeMaxDynamicSharedMemorySize, smem);
    main_k<<<NBLK, THR, smem>>>(sidx, adjw, W2, b2, W4, out);

    reduce_k<<<OUT_, 256>>>(gamma, beta);
    bn_k<<<(G_*OUT_/4)/256, 256>>>(out);
}

// round 7
// speedup vs baseline: 1.2354x; 1.2354x over previous
#include <cuda_runtime.h>
#include <math.h>
#include <float.h>

#define B_   16
#define C_   64
#define N_   2048
#define K_   20
#define OUT_ 128
#define G_   (B_*N_)          // 32768 columns
#define TN   8                // columns per block
#define NBLK (G_/TN)          // 4096
#define THR  256
#define FSTR 1284             // padded per-column stride (floats)
#define EPS_ 1e-5f

typedef unsigned long long u64;

// ---- packed fp32x2 helpers (sm_100+; ptxas never auto-fuses) ----
__device__ __forceinline__ u64 fma2(u64 a, u64 b, u64 c){
    u64 d; asm("fma.rn.f32x2 %0, %1, %2, %3;" : "=l"(d) : "l"(a), "l"(b), "l"(c)); return d;
}
__device__ __forceinline__ u64 pack2(float lo, float hi){
    u64 d; asm("mov.b64 %0, {%1,%2};" : "=l"(d) : "f"(lo), "f"(hi)); return d;
}
__device__ __forceinline__ float sum2(u64 d){
    float a, b; asm("mov.b64 {%0,%1}, %2;" : "=f"(a), "=f"(b) : "l"(d)); return a + b;
}

// ---- device scratch (no allocations allowed) ----
__device__ float g_xT[G_*C_];             // 8 MB: x transposed to (B*N, C)
__device__ float g_part[NBLK*OUT_*2];     // 4 MB: per-block (sum, sumsq) per channel
__device__ float g_scale[OUT_];
__device__ float g_shift[OUT_];

// ============================================================
// Kernel 0: transpose x (B,C,N) -> xT (B*N, C), smem-tiled
// ============================================================
__global__ void transpose_k(const float* __restrict__ x) {
    __shared__ float t[32][33];
    int b  = blockIdx.z;
    int n0 = blockIdx.x * 32, c0 = blockIdx.y * 32;
    int tx = threadIdx.x, ty = threadIdx.y;
    #pragma unroll
    for (int i = ty; i < 32; i += 8)
        t[i][tx] = x[((size_t)b*C_ + c0 + i)*N_ + n0 + tx];
    __syncthreads();
    #pragma unroll
    for (int i = ty; i < 32; i += 8)
        g_xT[((size_t)b*N_ + n0 + i)*C_ + c0 + tx] = t[tx][i];
}

// ============================================================
// Kernel 1: fused gather + feats + out2 + out4 (pre-BN) + partial stats
//   R3 thread map: o0 = tid>>3 (0..31), o1 = o0+32, col = tid&7.
//   f32x2 applied with spill-safe accumulator budgets.
// ============================================================
__global__ __launch_bounds__(THR, 2)
void main_k(const int*   __restrict__ sidx,
            const float* __restrict__ adjw,
            const float* __restrict__ W2,
            const float* __restrict__ b2,
            const float* __restrict__ W4,
            float*       __restrict__ out)
{
    extern __shared__ float sm[];
    float* S  = sm;                      // TN*FSTR: S[col][i*64+f]
    float* F  = S + TN*FSTR;             // TN*FSTR: feats[col][f*20+k]
    float* AW = F + TN*FSTR;             // 64*68: first A[col*400+..], later W4a rows (stride 68)
    float* XR = AW + 64*68;              // TN*64: x row per column

    const int tid = threadIdx.x;
    const int g0  = blockIdx.x * TN;

    // ---- gather spiral rows into S (float4, coalesced over xT rows) ----
    for (int j = tid; j < TN*K_*16; j += THR) {
        int col = j / (K_*16);
        int r   = j % (K_*16);
        int i   = r >> 4, q = r & 15;
        int p   = sidx[(g0 + col)*K_ + i];
        float4 v = ((const float4*)g_xT)[(size_t)p*16 + q];
        float* d = &S[col*FSTR + i*64 + q*4];
        d[0]=v.x; d[1]=v.y; d[2]=v.z; d[3]=v.w;
    }
    // ---- adjweight tile ----
    for (int j = tid; j < TN*100; j += THR) {
        int col = j/100, q = j%100;
        float4 v = ((const float4*)adjw)[(size_t)(g0+col)*100 + q];
        float* d = &AW[col*400 + q*4];
        d[0]=v.x; d[1]=v.y; d[2]=v.z; d[3]=v.w;
    }
    // ---- x rows ----
    for (int j = tid; j < TN*16; j += THR) {
        float4 v = ((const float4*)g_xT)[(size_t)(g0 + j/16)*16 + (j & 15)];
        float* d = &XR[(j/16)*64 + (j & 15)*4];
        d[0]=v.x; d[1]=v.y; d[2]=v.z; d[3]=v.w;
    }
    __syncthreads();

    // ---- feats[col][f*20+k] = sum_i S[col][i][f] * A[col][i][k]  (f32x2 over k)
    #pragma unroll
    for (int pass = 0; pass < 2; pass++) {
        int id   = tid + pass*THR;
        int fcol = id >> 6, f = id & 63;
        u64 acc[10];
        #pragma unroll
        for (int k = 0; k < 10; k++) acc[k] = 0ull;
        const float* Sc = S + fcol*FSTR + f;
        const u64*   Ac = (const u64*)(AW + fcol*400);   // broadcast across lanes
        #pragma unroll
        for (int i = 0; i < 20; i++) {
            float s = Sc[i*64];
            u64 sv = pack2(s, s);
            #pragma unroll
            for (int k = 0; k < 10; k++) acc[k] = fma2(sv, Ac[i*10 + k], acc[k]);
        }
        u64* Fd = (u64*)(F + fcol*FSTR + f*20);
        #pragma unroll
        for (int k = 0; k < 10; k++) Fd[k] = acc[k];
    }
    __syncthreads();

    // ---- stage W4a (first 64 cols of W4) into AW with padded stride 68 ----
    for (int j = tid; j < 64*16; j += THR) {
        int o = j >> 4, q = j & 15;
        float4 v = ((const float4*)W4)[o*32 + q];
        float* d = &AW[o*68 + q*4];
        d[0]=v.x; d[1]=v.y; d[2]=v.z; d[3]=v.w;
    }
    __syncthreads();

    const int o0  = tid >> 3;        // 0..31
    const int o1  = o0 + 32;         // 32..63
    const int col = tid & 7;
    const int g   = g0 + col;

    // ---- out2: W2 @ feats (f32x2, 4 u64 accum chains) ----
    float v20, v21;
    {
        const ulonglong2* w0 = (const ulonglong2*)(W2 + (size_t)o0*1280);
        const ulonglong2* w1 = (const ulonglong2*)(W2 + (size_t)o1*1280);
        const ulonglong2* fv = (const ulonglong2*)(F + col*FSTR);
        u64 a0x=0ull, a0y=0ull, a1x=0ull, a1y=0ull;
        #pragma unroll 4
        for (int q = 0; q < 320; q++) {
            ulonglong2 fq = fv[q];
            ulonglong2 u  = w0[q], v = w1[q];
            a0x = fma2(fq.x, u.x, a0x); a0y = fma2(fq.y, u.y, a0y);
            a1x = fma2(fq.x, v.x, a1x); a1y = fma2(fq.y, v.y, a1y);
        }
        v20 = sum2(a0x) + sum2(a0y) + b2[o0];
        v21 = sum2(a1x) + sum2(a1y) + b2[o1];
    }

    // ---- out4: max_k (W4a @ S_k), f32x2, k-chunks of 5 (20 u64 accum regs) ----
    float m0 = -FLT_MAX, m1 = -FLT_MAX;
    {
        const ulonglong2* wa = (const ulonglong2*)(AW + o0*68);
        const ulonglong2* wb = (const ulonglong2*)(AW + o1*68);
        #pragma unroll
        for (int kt = 0; kt < 4; kt++) {
            u64 s0[5], s1[5];
            #pragma unroll
            for (int k = 0; k < 5; k++) { s0[k]=0ull; s1[k]=0ull; }
            const float* Sb = S + col*FSTR + (kt*5)*64;
            #pragma unroll
            for (int q = 0; q < 16; q++) {
                ulonglong2 u = wa[q], v = wb[q];
                #pragma unroll
                for (int k = 0; k < 5; k++) {
                    ulonglong2 sv = ((const ulonglong2*)(Sb + k*64))[q];
                    s0[k] = fma2(sv.x, u.x, s0[k]); s0[k] = fma2(sv.y, u.y, s0[k]);
                    s1[k] = fma2(sv.x, v.x, s1[k]); s1[k] = fma2(sv.y, v.y, s1[k]);
                }
            }
            #pragma unroll
            for (int k = 0; k < 5; k++) {
                m0 = fmaxf(m0, sum2(s0[k]));
                m1 = fmaxf(m1, sum2(s1[k]));
            }
        }
    }

    // ---- dx = (W4b - W4a) @ x[:,n]  (k-invariant term, f32x2) ----
    float v40, v41;
    {
        const ulonglong2* w4g = (const ulonglong2*)W4;
        const ulonglong2* xr4 = (const ulonglong2*)(XR + col*64);
        u64 aA0=0ull, aB0=0ull, aA1=0ull, aB1=0ull;
        #pragma unroll
        for (int q = 0; q < 16; q++) {
            ulonglong2 xv = xr4[q];
            ulonglong2 A0 = w4g[o0*32 + q], Bv0 = w4g[o0*32 + 16 + q];
            ulonglong2 A1 = w4g[o1*32 + q], Bv1 = w4g[o1*32 + 16 + q];
            aA0 = fma2(xv.x, A0.x, aA0);  aA0 = fma2(xv.y, A0.y, aA0);
            aB0 = fma2(xv.x, Bv0.x, aB0); aB0 = fma2(xv.y, Bv0.y, aB0);
            aA1 = fma2(xv.x, A1.x, aA1);  aA1 = fma2(xv.y, A1.y, aA1);
            aB1 = fma2(xv.x, Bv1.x, aB1); aB1 = fma2(xv.y, Bv1.y, aB1);
        }
        v40 = m0 + (sum2(aB0) - sum2(aA0));
        v41 = m1 + (sum2(aB1) - sum2(aA1));
    }

    // ---- write pre-BN outputs ----
    {
        int b = g >> 11, n = g & 2047;
        size_t base = ((size_t)b*OUT_)*N_ + n;
        out[base + (size_t)o0*N_]        = v20;
        out[base + (size_t)o1*N_]        = v21;
        out[base + (size_t)(64+o0)*N_]   = v40;
        out[base + (size_t)(64+o1)*N_]   = v41;
    }

    // ---- deterministic per-block stats: butterfly over the 3 col bits ----
    float s20=v20, q20=v20*v20, s21=v21, q21=v21*v21;
    float s40=v40, q40=v40*v40, s41=v41, q41=v41*v41;
    #pragma unroll
    for (int off = 1; off < 8; off <<= 1) {
        s20 += __shfl_xor_sync(0xffffffffu, s20, off);
        q20 += __shfl_xor_sync(0xffffffffu, q20, off);
        s21 += __shfl_xor_sync(0xffffffffu, s21, off);
        q21 += __shfl_xor_sync(0xffffffffu, q21, off);
        s40 += __shfl_xor_sync(0xffffffffu, s40, off);
        q40 += __shfl_xor_sync(0xffffffffu, q40, off);
        s41 += __shfl_xor_sync(0xffffffffu, s41, off);
        q41 += __shfl_xor_sync(0xffffffffu, q41, off);
    }
    if (col == 0) {
        float* P = g_part + (size_t)blockIdx.x*(OUT_*2);
        P[o0*2]        = s20; P[o0*2 + 1]        = q20;
        P[o1*2]        = s21; P[o1*2 + 1]        = q21;
        P[(64+o0)*2]   = s40; P[(64+o0)*2 + 1]   = q40;
        P[(64+o1)*2]   = s41; P[(64+o1)*2 + 1]   = q41;
    }
}

// ============================================================
// Kernel 2: fixed-order reduction of partials -> scale/shift per channel
// ============================================================
__global__ void reduce_k(const float* __restrict__ gamma, const float* __restrict__ beta) {
    int ch = blockIdx.x;
    __shared__ float ss[256], sq[256];
    float s = 0.f, q = 0.f;
    for (int blk = threadIdx.x; blk < NBLK; blk += 256) {
        const float* P = g_part + (size_t)blk*(OUT_*2) + ch*2;
        s += P[0]; q += P[1];
    }
    ss[threadIdx.x] = s; sq[threadIdx.x] = q;
    __syncthreads();
    for (int off = 128; off > 0; off >>= 1) {
        if (threadIdx.x < off) {
            ss[threadIdx.x] += ss[threadIdx.x + off];
            sq[threadIdx.x] += sq[threadIdx.x + off];
        }
        __syncthreads();
    }
    if (threadIdx.x == 0) {
        float mean = ss[0] / (float)G_;
        float var  = sq[0] / (float)G_ - mean*mean;
        float sc   = gamma[ch] * rsqrtf(var + EPS_);
        g_scale[ch] = sc;
        g_shift[ch] = beta[ch] - mean*sc;
    }
}

// ============================================================
// Kernel 3: apply batchnorm in place (float4)
// ============================================================
__global__ void bn_k(float* __restrict__ out) {
    int i  = blockIdx.x*blockDim.x + threadIdx.x;     // over 1,048,576 float4
    int ch = (i >> 9) & 127;                          // 512 float4 per (b,ch) row
    float sc = g_scale[ch], sh = g_shift[ch];
    float4 v = ((float4*)out)[i];
    v.x = v.x*sc + sh; v.y = v.y*sc + sh;
    v.z = v.z*sc + sh; v.w = v.w*sc + sh;
    ((float4*)out)[i] = v;
}

// ============================================================
extern "C" void kernel_launch(void* const* d_in, const int* in_sizes, int n_in,
                              void* d_out, int out_size) {
    const float* x     = (const float*)d_in[0];
    const int*   sidx  = (const int*)  d_in[1];
    const float* adjw  = (const float*)d_in[2];
    const float* W2    = (const float*)d_in[3];
    const float* b2    = (const float*)d_in[4];
    const float* W4    = (const float*)d_in[5];
    const float* gamma = (const float*)d_in[6];
    const float* beta  = (const float*)d_in[7];
    float* out = (float*)d_out;

    dim3 tb(32, 8);
    dim3 tg(N_/32, C_/32, B_);
    transpose_k<<<tg, tb>>>(x);

    const int smem = (TN*FSTR*2 + 64*68 + TN*64) * (int)sizeof(float); // 101,632 B
    cudaFuncSetAttribute(main_k, cudaFuncAttributeMaxDynamicSharedMemorySize, smem);
    main_k<<<NBLK, THR, smem>>>(sidx, adjw, W2, b2, W4, out);

    reduce_k<<<OUT_, 256>>>(gamma, beta);
    bn_k<<<(G_*OUT_/4)/256, 256>>>(out);
}

// round 8
// speedup vs baseline: 1.9126x; 1.5482x over previous
#include <cuda_runtime.h>
#include <math.h>
#include <float.h>

#define B_   16
#define C_   64
#define N_   2048
#define K_   20
#define OUT_ 128
#define G_   (B_*N_)          // 32768 columns
#define TN   8                // columns per block
#define NBLK (G_/TN)          // 4096
#define THR  256
#define FSTR 1284             // padded per-column stride (floats)
#define EPS_ 1e-5f

// ---- device scratch (no allocations allowed) ----
__device__ float g_xT[G_*C_];             // 8 MB: x transposed to (B*N, C)
__device__ float g_P[G_*64];              // 8 MB: P[p][o] = W4a . xT[p]
__device__ float g_Q[G_*64];              // 8 MB: Q[g][o] = (W4b-W4a) . xT[g]
__device__ float g_part[NBLK*OUT_*2];     // 4 MB: per-block (sum, sumsq) per channel
__device__ float g_scale[OUT_];
__device__ float g_shift[OUT_];

// ============================================================
// Kernel 0: transpose x (B,C,N) -> xT (B*N, C), smem-tiled
// ============================================================
__global__ void transpose_k(const float* __restrict__ x) {
    __shared__ float t[32][33];
    int b  = blockIdx.z;
    int n0 = blockIdx.x * 32, c0 = blockIdx.y * 32;
    int tx = threadIdx.x, ty = threadIdx.y;
    #pragma unroll
    for (int i = ty; i < 32; i += 8)
        t[i][tx] = x[((size_t)b*C_ + c0 + i)*N_ + n0 + tx];
    __syncthreads();
    #pragma unroll
    for (int i = ty; i < 32; i += 8)
        g_xT[((size_t)b*N_ + n0 + i)*C_ + c0 + tx] = t[tx][i];
}

// ============================================================
// Kernel 0b: P/Q precompute.  P[p][o] = sum_c W4a[o][c] xT[p][c],
//            Q[p][o] = sum_c (W4b-W4a)[o][c] xT[p][c].
// One block = 64 p-rows; W4-derived rows + xT tile staged in smem.
// ============================================================
__global__ __launch_bounds__(256)
void pq_k(const float* __restrict__ W4) {
    __shared__ float X[64*68];
    __shared__ float WW[128*68];
    const int tid = threadIdx.x;
    const int p0  = blockIdx.x * 64;

    // WW rows 0..63 = W4a, rows 64..127 = W4b - W4a
    for (int j = tid; j < 64*16; j += 256) {
        int o = j >> 4, q = j & 15;
        float4 a = ((const float4*)W4)[o*32 + q];        // W4[o][4q..4q+3]
        float4 b = ((const float4*)W4)[o*32 + 16 + q];   // W4[o][64+4q..]
        float* d = &WW[o*68 + q*4];
        d[0]=a.x; d[1]=a.y; d[2]=a.z; d[3]=a.w;
        float* e = &WW[(64+o)*68 + q*4];
        e[0]=b.x-a.x; e[1]=b.y-a.y; e[2]=b.z-a.z; e[3]=b.w-a.w;
    }
    for (int j = tid; j < 64*16; j += 256) {
        int r = j >> 4, q = j & 15;
        float4 v = ((const float4*)g_xT)[(size_t)(p0 + r)*16 + q];
        float* d = &X[r*68 + q*4];
        d[0]=v.x; d[1]=v.y; d[2]=v.z; d[3]=v.w;
    }
    __syncthreads();

    const int o  = tid & 63;
    const int ps = tid >> 6;                 // 0..3 -> 16 p-rows each
    const float4* wa = (const float4*)(WW + o*68);
    const float4* wb = (const float4*)(WW + (64+o)*68);
    for (int pl = 0; pl < 16; pl++) {
        int p = ps*16 + pl;
        const float4* xv = (const float4*)(X + p*68);
        float aA0=0.f, aA1=0.f, aB0=0.f, aB1=0.f;
        #pragma unroll
        for (int q = 0; q < 16; q++) {
            float4 xq = xv[q], u = wa[q], v = wb[q];
            aA0 += xq.x*u.x + xq.y*u.y;  aA1 += xq.z*u.z + xq.w*u.w;
            aB0 += xq.x*v.x + xq.y*v.y;  aB1 += xq.z*v.z + xq.w*v.w;
        }
        g_P[(size_t)(p0 + p)*64 + o] = aA0 + aA1;
        g_Q[(size_t)(p0 + p)*64 + o] = aB0 + aB1;
    }
}

// ============================================================
// Kernel 1: fused gather + feats + out2 + out4-combine + partial stats
//   thread map: o0 = tid>>3 (0..31), o1 = o0+32, col = tid&7.
//   out4 is now: max over 20 gathered P values + Q (no per-column GEMM).
// ============================================================
__global__ __launch_bounds__(THR, 2)
void main_k(const int*   __restrict__ sidx,
            const float* __restrict__ adjw,
            const float* __restrict__ W2,
            const float* __restrict__ b2,
            float*       __restrict__ out)
{
    extern __shared__ float sm[];
    float* S  = sm;                      // TN*FSTR: S[col][i*64+f]
    float* F  = S + TN*FSTR;             // TN*FSTR: feats[col][f*20+k]
    float* AW = F + TN*FSTR;             // TN*400: A[col][i*20+k]
    int*   SX = (int*)(AW + TN*400);     // TN*20 spiral indices

    const int tid = threadIdx.x;
    const int g0  = blockIdx.x * TN;

    // ---- stage spiral indices ----
    if (tid < TN*K_) SX[tid] = sidx[g0*K_ + tid];      // SX[col*20+i]

    // ---- gather spiral rows into S (float4, coalesced over xT rows) ----
    for (int j = tid; j < TN*K_*16; j += THR) {
        int col = j / (K_*16);
        int r   = j % (K_*16);
        int i   = r >> 4, q = r & 15;
        int p   = sidx[(g0 + col)*K_ + i];
        float4 v = ((const float4*)g_xT)[(size_t)p*16 + q];
        float* d = &S[col*FSTR + i*64 + q*4];
        d[0]=v.x; d[1]=v.y; d[2]=v.z; d[3]=v.w;
    }
    // ---- adjweight tile ----
    for (int j = tid; j < TN*100; j += THR) {
        int col = j/100, q = j%100;
        float4 v = ((const float4*)adjw)[(size_t)(g0+col)*100 + q];
        float* d = &AW[col*400 + q*4];
        d[0]=v.x; d[1]=v.y; d[2]=v.z; d[3]=v.w;
    }
    __syncthreads();

    // ---- feats[col][f*20+k] = sum_i S[col][i][f] * A[col][i][k] ----
    #pragma unroll
    for (int pass = 0; pass < 2; pass++) {
        int id   = tid + pass*THR;
        int fcol = id >> 6, f = id & 63;
        float acc[20];
        #pragma unroll
        for (int k = 0; k < 20; k++) acc[k] = 0.f;
        const float* Sc = S  + fcol*FSTR + f;
        const float* Ac = AW + fcol*400;
        #pragma unroll
        for (int i = 0; i < 20; i++) {
            float sv = Sc[i*64];
            #pragma unroll
            for (int k = 0; k < 20; k++) acc[k] += sv * Ac[i*20 + k];
        }
        float* Fd = F + fcol*FSTR + f*20;
        #pragma unroll
        for (int k = 0; k < 20; k++) Fd[k] = acc[k];
    }
    __syncthreads();

    const int o0  = tid >> 3;        // 0..31
    const int o1  = o0 + 32;         // 32..63
    const int col = tid & 7;
    const int g   = g0 + col;

    // ---- out2: W2 @ feats  (8 independent accum chains) ----
    float a0x=0.f,a0y=0.f,a0z=0.f,a0w=0.f;
    float a1x=0.f,a1y=0.f,a1z=0.f,a1w=0.f;
    {
        const float4* w0 = (const float4*)(W2 + (size_t)o0*1280);
        const float4* w1 = (const float4*)(W2 + (size_t)o1*1280);
        const float4* fv = (const float4*)(F + col*FSTR);
        #pragma unroll 8
        for (int q = 0; q < 320; q++) {
            float4 fq = fv[q];
            float4 u  = w0[q], v = w1[q];
            a0x += fq.x*u.x; a0y += fq.y*u.y; a0z += fq.z*u.z; a0w += fq.w*u.w;
            a1x += fq.x*v.x; a1y += fq.y*v.y; a1z += fq.z*v.z; a1w += fq.w*v.w;
        }
    }
    float v20 = a0x + a0y + a0z + a0w + b2[o0];
    float v21 = a1x + a1y + a1z + a1w + b2[o1];

    // ---- out4: max over 20 gathered P values (chunks of 10 for MLP) + Q ----
    float m0 = -FLT_MAX, m1 = -FLT_MAX;
    {
        const int* sxc = SX + col*K_;
        #pragma unroll
        for (int half = 0; half < 2; half++) {
            float pv0[10], pv1[10];
            #pragma unroll
            for (int i = 0; i < 10; i++) {
                size_t p = (size_t)sxc[half*10 + i] * 64;
                pv0[i] = __ldg(&g_P[p + o0]);
                pv1[i] = __ldg(&g_P[p + o1]);
            }
            #pragma unroll
            for (int i = 0; i < 10; i++) {
                m0 = fmaxf(m0, pv0[i]);
                m1 = fmaxf(m1, pv1[i]);
            }
        }
    }
    float v40 = m0 + g_Q[(size_t)g*64 + o0];
    float v41 = m1 + g_Q[(size_t)g*64 + o1];

    // ---- write pre-BN outputs ----
    {
        int b = g >> 11, n = g & 2047;
        size_t base = ((size_t)b*OUT_)*N_ + n;
        out[base + (size_t)o0*N_]        = v20;
        out[base + (size_t)o1*N_]        = v21;
        out[base + (size_t)(64+o0)*N_]   = v40;
        out[base + (size_t)(64+o1)*N_]   = v41;
    }

    // ---- deterministic per-block stats: butterfly over the 3 col bits ----
    float s20=v20, q20=v20*v20, s21=v21, q21=v21*v21;
    float s40=v40, q40=v40*v40, s41=v41, q41=v41*v41;
    #pragma unroll
    for (int off = 1; off < 8; off <<= 1) {
        s20 += __shfl_xor_sync(0xffffffffu, s20, off);
        q20 += __shfl_xor_sync(0xffffffffu, q20, off);
        s21 += __shfl_xor_sync(0xffffffffu, s21, off);
        q21 += __shfl_xor_sync(0xffffffffu, q21, off);
        s40 += __shfl_xor_sync(0xffffffffu, s40, off);
        q40 += __shfl_xor_sync(0xffffffffu, q40, off);
        s41 += __shfl_xor_sync(0xffffffffu, s41, off);
        q41 += __shfl_xor_sync(0xffffffffu, q41, off);
    }
    if (col == 0) {
        float* P = g_part + (size_t)blockIdx.x*(OUT_*2);
        P[o0*2]        = s20; P[o0*2 + 1]        = q20;
        P[o1*2]        = s21; P[o1*2 + 1]        = q21;
        P[(64+o0)*2]   = s40; P[(64+o0)*2 + 1]   = q40;
        P[(64+o1)*2]   = s41; P[(64+o1)*2 + 1]   = q41;
    }
}

// ============================================================
// Kernel 2: fixed-order reduction of partials -> scale/shift per channel
// ============================================================
__global__ void reduce_k(const float* __restrict__ gamma, const float* __restrict__ beta) {
    int ch = blockIdx.x;
    __shared__ float ss[256], sq[256];
    float s = 0.f, q = 0.f;
    for (int blk = threadIdx.x; blk < NBLK; blk += 256) {
        const float* P = g_part + (size_t)blk*(OUT_*2) + ch*2;
        s += P[0]; q += P[1];
    }
    ss[threadIdx.x] = s; sq[threadIdx.x] = q;
    __syncthreads();
    for (int off = 128; off > 0; off >>= 1) {
        if (threadIdx.x < off) {
            ss[threadIdx.x] += ss[threadIdx.x + off];
            sq[threadIdx.x] += sq[threadIdx.x + off];
        }
        __syncthreads();
    }
    if (threadIdx.x == 0) {
        float mean = ss[0] / (float)G_;
        float var  = sq[0] / (float)G_ - mean*mean;
        float sc   = gamma[ch] * rsqrtf(var + EPS_);
        g_scale[ch] = sc;
        g_shift[ch] = beta[ch] - mean*sc;
    }
}

// ============================================================
// Kernel 3: apply batchnorm in place (float4)
// ============================================================
__global__ void bn_k(float* __restrict__ out) {
    int i  = blockIdx.x*blockDim.x + threadIdx.x;     // over 1,048,576 float4
    int ch = (i >> 9) & 127;                          // 512 float4 per (b,ch) row
    float sc = g_scale[ch], sh = g_shift[ch];
    float4 v = ((float4*)out)[i];
    v.x = v.x*sc + sh; v.y = v.y*sc + sh;
    v.z = v.z*sc + sh; v.w = v.w*sc + sh;
    ((float4*)out)[i] = v;
}

// ============================================================
extern "C" void kernel_launch(void* const* d_in, const int* in_sizes, int n_in,
                              void* d_out, int out_size) {
    const float* x     = (const float*)d_in[0];
    const int*   sidx  = (const int*)  d_in[1];
    const float* adjw  = (const float*)d_in[2];
    const float* W2    = (const float*)d_in[3];
    const float* b2    = (const float*)d_in[4];
    const float* W4    = (const float*)d_in[5];
    const float* gamma = (const float*)d_in[6];
    const float* beta  = (const float*)d_in[7];
    float* out = (float*)d_out;

    dim3 tb(32, 8);
    dim3 tg(N_/32, C_/32, B_);
    transpose_k<<<tg, tb>>>(x);

    pq_k<<<G_/64, 256>>>(W4);

    const int smem = (TN*FSTR*2 + TN*400) * (int)sizeof(float) + TN*K_*(int)sizeof(int); // 95,616 B
    cudaFuncSetAttribute(main_k, cudaFuncAttributeMaxDynamicSharedMemorySize, smem);
    main_k<<<NBLK, THR, smem>>>(sidx, adjw, W2, b2, out);

    reduce_k<<<OUT_, 256>>>(gamma, beta);
    bn_k<<<(G_*OUT_/4)/256, 256>>>(out);
}